// round 8
// baseline (speedup 1.0000x reference)
#include <cuda_runtime.h>
#include <cuda_bf16.h>
#include <math.h>
#include <stdint.h>

// ===========================================================================
// Fused INR via warp-level mma.sync (bf16 hi/lo 3-product split, fp32 accum).
// R7: 32-point CTAs (256 thr, 8 warps), 2 CTAs/SM so barriers/epilogues of
//     one CTA overlap MMAs of the other. Same total MMA work as R6.
// ===========================================================================

#define OMEGA0    30.0f
#define TWO_PI_F  6.283185307179586f
#define THREADS   256

#define NTILES    (512 + 5 * 1024)      // 5632 (mt,ks) tiles total
#define PLANE_U32 (NTILES * 128)        // u32 per plane (tile=128 u32)

__device__ __align__(16) uint32_t g_wfrag[2 * PLANE_U32];   // hi plane, lo plane

// ---- SMEM layout (bytes) ----
#define SM_WOUT  0                       // 1536 floats (6144 B)
#define SM_CS    6144                    // 96 floats
#define SM_BFF   6528                    // 384 floats
#define SM_HI    8192                    // act hi: 512 rows x 64B = 32768
#define SM_LO    (SM_HI + 32768)
#define SMEM_BYTES (SM_LO + 32768)       // 73728

// ---------------- helpers ----------------
__device__ __forceinline__ uint32_t smem_u32(const void* p) {
    uint32_t a;
    asm("{ .reg .u64 t; cvta.to.shared.u64 t, %1; cvt.u32.u64 %0, t; }"
        : "=r"(a) : "l"(p));
    return a;
}
__device__ __forceinline__ void mma16816(float* d, const uint4& a,
                                         uint32_t b0, uint32_t b1) {
    asm volatile(
        "mma.sync.aligned.m16n8k16.row.col.f32.bf16.bf16.f32 "
        "{%0,%1,%2,%3}, {%4,%5,%6,%7}, {%8,%9}, {%0,%1,%2,%3};"
        : "+f"(d[0]), "+f"(d[1]), "+f"(d[2]), "+f"(d[3])
        : "r"(a.x), "r"(a.y), "r"(a.z), "r"(a.w), "r"(b0), "r"(b1));
}
__device__ __forceinline__ void ldmx4t(uint32_t& r0, uint32_t& r1,
                                       uint32_t& r2, uint32_t& r3,
                                       uint32_t addr) {
    asm volatile(
        "ldmatrix.sync.aligned.m8n8.x4.trans.shared.b16 {%0,%1,%2,%3}, [%4];"
        : "=r"(r0), "=r"(r1), "=r"(r2), "=r"(r3) : "r"(addr));
}
__device__ __forceinline__ uint16_t bfb(float v) {
    __nv_bfloat16 h = __float2bfloat16(v);
    return *reinterpret_cast<uint16_t*>(&h);
}
__device__ __forceinline__ float bff2f(uint16_t b) {
    __nv_bfloat16 h = *reinterpret_cast<__nv_bfloat16*>(&b);
    return __bfloat162float(h);
}

// act offset for (row k, col n): 64B rows, XOR swizzle on (row&3)
__device__ __forceinline__ uint32_t act_off(int row, int n) {
    return (uint32_t)row * 64u + (((uint32_t)n * 2u) ^ (((uint32_t)row & 3u) << 4));
}

// store v to (row, n) in both planes (hi + residual lo)
__device__ __forceinline__ void store1(unsigned char* sm, int row, int n, float v) {
    uint32_t off = act_off(row, n);
    uint16_t hb = bfb(v);
    *(uint16_t*)(sm + SM_HI + off) = hb;
    *(uint16_t*)(sm + SM_LO + off) = bfb(v - bff2f(hb));
}

// ---------------- weight prep: fp32 -> fragment-ordered bf16 hi/lo ----------
__global__ void prep_weights(const float* __restrict__ Wf,
                             const float* __restrict__ Wh) {
    int idx = blockIdx.x * blockDim.x + threadIdx.x;
    if (idx >= 2 * PLANE_U32) return;
    int p   = idx / PLANE_U32;
    int rem = idx - p * PLANE_U32;
    int tile = rem >> 7;
    int li   = rem & 127;
    int lane = li >> 2, q = li & 3;

    const float* src; int K, mt, ks;
    if (tile < 512) { mt = tile >> 4; ks = tile & 15; K = 256; src = Wf; }
    else {
        int th = tile - 512;
        int l = th >> 10, tt = th & 1023;
        mt = tt >> 5; ks = tt & 31; K = 512;
        src = Wh + (size_t)l * 512 * 512;
    }
    int r  = lane >> 2, c2 = (lane & 3) * 2;
    int row = mt * 16 + r + (q & 1) * 8;
    int k   = ks * 16 + c2 + (q >> 1) * 8;
    float w0 = src[(size_t)row * K + k];
    float w1 = src[(size_t)row * K + k + 1];
    uint16_t h0 = bfb(w0), h1 = bfb(w1);
    uint16_t o0, o1;
    if (p == 0) { o0 = h0; o1 = h1; }
    else        { o0 = bfb(w0 - bff2f(h0)); o1 = bfb(w1 - bff2f(h1)); }
    g_wfrag[idx] = ((uint32_t)o1 << 16) | (uint32_t)o0;
}

// ---------------- one sine layer (KS k-steps of 16) ----------------
template <int KS>
__device__ __forceinline__ void run_layer(
    unsigned char* sm, uint32_t shi, uint32_t slo,
    const uint32_t* __restrict__ whi,
    const uint32_t* __restrict__ wlo,
    const float* __restrict__ bias,
    int wid, int lane)
{
    float acc[4][4][4];     // [m-tile][n-tile][frag]
#pragma unroll
    for (int a = 0; a < 4; ++a)
#pragma unroll
        for (int b = 0; b < 4; ++b)
#pragma unroll
            for (int c = 0; c < 4; ++c) acc[a][b][c] = 0.0f;

    const int r  = lane >> 2;
    const int cq = lane & 3;
    const int mid  = lane >> 3;
    const int rrow = lane & 7;
    const uint32_t rswz = ((uint32_t)rrow & 3u) << 4;
    const uint32_t krow_off = ((uint32_t)((mid & 1) * 8 + rrow)) * 64u;
    const uint32_t nb_base  = (uint32_t)((mid >> 1) * 8) * 2u;

    // A fragment base for this warp (4 m-tiles, strided KS*128 u32 apart)
    const uint32_t* pAh = whi + (size_t)(wid * 4) * KS * 128 + lane * 4;
    const uint32_t* pAl = wlo + (size_t)(wid * 4) * KS * 128 + lane * 4;

    // prefetch first m-tile of ks=0
    uint4 Ah = *(const uint4*)pAh;
    uint4 Al = *(const uint4*)pAl;

#pragma unroll 1
    for (int ks = 0; ks < KS; ++ks) {
        // ---- B fragments for this k-step: 2 n-groups x 2 planes ----
        uint32_t Bh[8], Bl[8];
        const uint32_t kbase = (uint32_t)ks * 16u * 64u + krow_off;
#pragma unroll
        for (int j = 0; j < 2; ++j) {
            uint32_t nb = ((uint32_t)j * 32u + nb_base) ^ rswz;
            ldmx4t(Bh[4 * j], Bh[4 * j + 1], Bh[4 * j + 2], Bh[4 * j + 3],
                   shi + kbase + nb);
            ldmx4t(Bl[4 * j], Bl[4 * j + 1], Bl[4 * j + 2], Bl[4 * j + 3],
                   slo + kbase + nb);
        }

#pragma unroll
        for (int mt = 0; mt < 4; ++mt) {
            // prefetch next A fragment (next m-tile, or mt=0 of next k-step)
            uint4 nAh, nAl;
            const int nmt = (mt + 1) & 3;
            const int nks = (mt == 3) ? ks + 1 : ks;
            if (nks < KS) {
                size_t o = (size_t)nmt * KS * 128 + (size_t)nks * 128;
                nAh = *(const uint4*)(pAh + o);
                nAl = *(const uint4*)(pAl + o);
            }
#pragma unroll
            for (int nt = 0; nt < 4; ++nt) {
                const uint32_t bh0 = Bh[nt * 2], bh1 = Bh[nt * 2 + 1];
                const uint32_t bl0 = Bl[nt * 2], bl1 = Bl[nt * 2 + 1];
                mma16816(acc[mt][nt], Ah, bh0, bh1);
                mma16816(acc[mt][nt], Ah, bl0, bl1);
                mma16816(acc[mt][nt], Al, bh0, bh1);
            }
            Ah = nAh; Al = nAl;
        }
    }

    // ---- sin + hi/lo split into acc regs BEFORE the read-barrier ----
#pragma unroll
    for (int mt = 0; mt < 4; ++mt) {
        const int row0 = wid * 64 + mt * 16 + r;
        const float ob0 = OMEGA0 * __ldg(bias + row0);
        const float ob1 = OMEGA0 * __ldg(bias + row0 + 8);
#pragma unroll
        for (int nt = 0; nt < 4; ++nt) {
            float v00 = __sinf(fmaf(OMEGA0, acc[mt][nt][0], ob0));
            float v01 = __sinf(fmaf(OMEGA0, acc[mt][nt][1], ob0));
            float v10 = __sinf(fmaf(OMEGA0, acc[mt][nt][2], ob1));
            float v11 = __sinf(fmaf(OMEGA0, acc[mt][nt][3], ob1));
            uint16_t h00 = bfb(v00), h01 = bfb(v01);
            uint16_t h10 = bfb(v10), h11 = bfb(v11);
            uint32_t l00 = (uint32_t)bfb(v00 - bff2f(h00));
            uint32_t l01 = (uint32_t)bfb(v01 - bff2f(h01));
            uint32_t l10 = (uint32_t)bfb(v10 - bff2f(h10));
            uint32_t l11 = (uint32_t)bfb(v11 - bff2f(h11));
            acc[mt][nt][0] = __uint_as_float(((uint32_t)h01 << 16) | h00);
            acc[mt][nt][1] = __uint_as_float(((uint32_t)h11 << 16) | h10);
            acc[mt][nt][2] = __uint_as_float((l01 << 16) | l00);
            acc[mt][nt][3] = __uint_as_float((l11 << 16) | l10);
        }
    }
    __syncthreads();   // all reads of act done -> safe to overwrite in place

#pragma unroll
    for (int mt = 0; mt < 4; ++mt) {
        const int row0 = wid * 64 + mt * 16 + r;
        const int row1 = row0 + 8;
#pragma unroll
        for (int nt = 0; nt < 4; ++nt) {
            const int n = nt * 8 + cq * 2;
            uint32_t off0 = act_off(row0, n);
            uint32_t off1 = act_off(row1, n);
            *(uint32_t*)(sm + SM_HI + off0) = __float_as_uint(acc[mt][nt][0]);
            *(uint32_t*)(sm + SM_HI + off1) = __float_as_uint(acc[mt][nt][1]);
            *(uint32_t*)(sm + SM_LO + off0) = __float_as_uint(acc[mt][nt][2]);
            *(uint32_t*)(sm + SM_LO + off1) = __float_as_uint(acc[mt][nt][3]);
        }
    }
    __syncthreads();   // next layer may read
}

// ---------------- main kernel ----------------
__global__ void __launch_bounds__(THREADS, 2)
inr_mma_kernel(const float* __restrict__ coords,
               const float* __restrict__ B_ff,
               const float* __restrict__ b_first,
               const float* __restrict__ b_hidden,
               const float* __restrict__ W_out,
               const float* __restrict__ b_out,
               float* __restrict__ out, int L)
{
    extern __shared__ unsigned char sm[];
    float* wout = (float*)(sm + SM_WOUT);
    float* cs   = (float*)(sm + SM_CS);
    float* bff  = (float*)(sm + SM_BFF);
    const uint32_t shi = smem_u32(sm + SM_HI);
    const uint32_t slo = smem_u32(sm + SM_LO);

    const int tid  = threadIdx.x;
    const int wid  = tid >> 5;
    const int lane = tid & 31;
    const int p0   = blockIdx.x * 32;

    if (tid < 96) {
        int g = p0 * 3 + tid;
        cs[tid] = (g < L * 3) ? coords[g] : 0.0f;
    }
    for (int i = tid; i < 384; i += THREADS) bff[i] = B_ff[i];
    __syncthreads();

    // Fourier features. sin(2*pi*t) == sin(2*pi*(t - rint(t))): exact
    // reduction before the 2*pi scale keeps the fast __sinf path accurate.
    for (int e = tid; e < 4096; e += THREADS) {
        int j = e >> 5, m = e & 31;
        float t = cs[m * 3 + 0] * bff[j] +
                  cs[m * 3 + 1] * bff[128 + j] +
                  cs[m * 3 + 2] * bff[256 + j];
        float f = t - rintf(t);
        float ang = TWO_PI_F * f;
        store1(sm, j, m, __sinf(ang));
        store1(sm, 128 + j, m, __cosf(ang));
    }
    __syncthreads();

    // layer 0: K=256 (16 k-steps)
    run_layer<16>(sm, shi, slo, g_wfrag, g_wfrag + PLANE_U32, b_first, wid, lane);
    // hidden layers: K=512 (32 k-steps)
#pragma unroll 1
    for (int l = 0; l < 5; ++l) {
        const size_t base = (size_t)(512 + l * 1024) * 128;
        run_layer<32>(sm, shi, slo, g_wfrag + base,
                      g_wfrag + PLANE_U32 + base,
                      b_hidden + l * 512, wid, lane);
    }

    // output linear 512 -> 3 (fp32, hi+lo reconstruct)
    for (int f = tid; f < 1536; f += THREADS) wout[f] = W_out[f];
    __syncthreads();
    if (tid < 96) {
        const int p = tid & 31, o = tid >> 5;
        float acc = 0.0f;
#pragma unroll 4
        for (int k = 0; k < 512; ++k) {
            uint32_t off = act_off(k, p);
            float h = bff2f(*(uint16_t*)(sm + SM_HI + off)) +
                      bff2f(*(uint16_t*)(sm + SM_LO + off));
            acc = fmaf(h, wout[o * 512 + k], acc);
        }
        int gp = p0 + p;
        if (gp < L) out[gp * 3 + o] = acc + __ldg(b_out + o);
    }
}

// ---------------- launcher ----------------
extern "C" void kernel_launch(void* const* d_in, const int* in_sizes, int n_in,
                              void* d_out, int out_size) {
    const float* coords   = (const float*)d_in[0];
    const float* B_ff     = (const float*)d_in[1];
    const float* W_first  = (const float*)d_in[2];
    const float* b_first  = (const float*)d_in[3];
    const float* W_hidden = (const float*)d_in[4];
    const float* b_hidden = (const float*)d_in[5];
    const float* W_out    = (const float*)d_in[6];
    const float* b_out    = (const float*)d_in[7];
    float* out = (float*)d_out;

    int L = in_sizes[0] / 3;
    int tiles = (L + 31) / 32;

    const int prep_n = 2 * PLANE_U32;
    prep_weights<<<(prep_n + 255) / 256, 256>>>(W_first, W_hidden);

    cudaFuncSetAttribute(inr_mma_kernel,
                         cudaFuncAttributeMaxDynamicSharedMemorySize,
                         SMEM_BYTES);
    inr_mma_kernel<<<tiles, THREADS, SMEM_BYTES>>>(
        coords, B_ff, b_first, b_hidden, W_out, b_out, out, L);
}

// round 9
// speedup vs baseline: 1.0403x; 1.0403x over previous
#include <cuda_runtime.h>
#include <cuda_bf16.h>
#include <math.h>
#include <stdint.h>

// ===========================================================================
// Fused INR via warp-level mma.sync (bf16 hi/lo 3-product split, fp32 accum).
// R8 = R6 geometry (64-pt CTA, 512 thr, warp = 2mt x 8nt) +
//   * MMA product interleave (acc reuse distance 8, not 1)
//   * epilogue diet: truncation-split + PRMT hi-pack + cvt.rn.bf16x2 lo-pack
//   * output layer parallelized over all 512 threads (shfl reduce)
// ===========================================================================

#define OMEGA0    30.0f
#define TWO_PI_F  6.283185307179586f
#define THREADS   512

#define NTILES    (512 + 5 * 1024)      // 5632 (mt,ks) tiles total
#define PLANE_U32 (NTILES * 128)        // u32 per plane (tile=128 u32)

__device__ __align__(16) uint32_t g_wfrag[2 * PLANE_U32];   // hi plane, lo plane

// ---- SMEM layout (bytes) ----
#define SM_WOUT  0                       // 1536 floats
#define SM_CS    6144                    // 192 floats
#define SM_BFF   6912                    // 384 floats
#define SM_HI    9216                    // act hi plane: 512 rows x 128B
#define SM_LO    (SM_HI + 65536)
#define SMEM_BYTES (SM_LO + 65536)       // 140288

// ---------------- helpers ----------------
__device__ __forceinline__ uint32_t smem_u32(const void* p) {
    uint32_t a;
    asm("{ .reg .u64 t; cvta.to.shared.u64 t, %1; cvt.u32.u64 %0, t; }"
        : "=r"(a) : "l"(p));
    return a;
}
__device__ __forceinline__ void mma16816(float* d, const uint4& a,
                                         uint32_t b0, uint32_t b1) {
    asm volatile(
        "mma.sync.aligned.m16n8k16.row.col.f32.bf16.bf16.f32 "
        "{%0,%1,%2,%3}, {%4,%5,%6,%7}, {%8,%9}, {%0,%1,%2,%3};"
        : "+f"(d[0]), "+f"(d[1]), "+f"(d[2]), "+f"(d[3])
        : "r"(a.x), "r"(a.y), "r"(a.z), "r"(a.w), "r"(b0), "r"(b1));
}
__device__ __forceinline__ void ldmx4t(uint32_t& r0, uint32_t& r1,
                                       uint32_t& r2, uint32_t& r3,
                                       uint32_t addr) {
    asm volatile(
        "ldmatrix.sync.aligned.m8n8.x4.trans.shared.b16 {%0,%1,%2,%3}, [%4];"
        : "=r"(r0), "=r"(r1), "=r"(r2), "=r"(r3) : "r"(addr));
}
__device__ __forceinline__ uint16_t bfb(float v) {
    __nv_bfloat16 h = __float2bfloat16(v);
    return *reinterpret_cast<uint16_t*>(&h);
}
__device__ __forceinline__ float bff2f(uint16_t b) {
    __nv_bfloat16 h = *reinterpret_cast<__nv_bfloat16*>(&b);
    return __bfloat162float(h);
}

// store v to (row, col n) in both planes (hi + residual lo), swizzled
__device__ __forceinline__ void store1(unsigned char* sm, int row, int n, float v) {
    uint32_t off = (uint32_t)row * 128u + (((uint32_t)n * 2u) ^ (((uint32_t)row & 7u) << 4));
    float hv; uint16_t hb = bfb(v); hv = bff2f(hb);
    *(uint16_t*)(sm + SM_HI + off) = hb;
    *(uint16_t*)(sm + SM_LO + off) = bfb(v - hv);
}

// ---------------- weight prep: fp32 -> fragment-ordered bf16 hi/lo ----------
__global__ void prep_weights(const float* __restrict__ Wf,
                             const float* __restrict__ Wh) {
    int idx = blockIdx.x * blockDim.x + threadIdx.x;
    if (idx >= 2 * PLANE_U32) return;
    int p   = idx / PLANE_U32;
    int rem = idx - p * PLANE_U32;
    int tile = rem >> 7;
    int li   = rem & 127;
    int lane = li >> 2, q = li & 3;

    const float* src; int K, mt, ks;
    if (tile < 512) { mt = tile >> 4; ks = tile & 15; K = 256; src = Wf; }
    else {
        int th = tile - 512;
        int l = th >> 10, tt = th & 1023;
        mt = tt >> 5; ks = tt & 31; K = 512;
        src = Wh + (size_t)l * 512 * 512;
    }
    int r  = lane >> 2, c2 = (lane & 3) * 2;
    int row = mt * 16 + r + (q & 1) * 8;
    int k   = ks * 16 + c2 + (q >> 1) * 8;
    float w0 = src[(size_t)row * K + k];
    float w1 = src[(size_t)row * K + k + 1];
    uint16_t h0 = bfb(w0), h1 = bfb(w1);
    uint16_t o0, o1;
    if (p == 0) { o0 = h0; o1 = h1; }
    else        { o0 = bfb(w0 - bff2f(h0)); o1 = bfb(w1 - bff2f(h1)); }
    g_wfrag[idx] = ((uint32_t)o1 << 16) | (uint32_t)o0;
}

// ---------------- one sine layer (KS k-steps of 16) ----------------
template <int KS>
__device__ __forceinline__ void run_layer(
    unsigned char* sm, uint32_t shi, uint32_t slo,
    const uint32_t* __restrict__ whi,
    const uint32_t* __restrict__ wlo,
    const float* __restrict__ bias,
    int wid, int lane)
{
    float acc[2][8][4];
#pragma unroll
    for (int a = 0; a < 2; ++a)
#pragma unroll
        for (int b = 0; b < 8; ++b)
#pragma unroll
            for (int c = 0; c < 4; ++c) acc[a][b][c] = 0.0f;

    const int r  = lane >> 2;
    const int cq = lane & 3;
    const int mid  = lane >> 3;
    const int rrow = lane & 7;
    const uint32_t rswz = (uint32_t)rrow << 4;
    const uint32_t krow_off = ((uint32_t)((mid & 1) * 8 + rrow)) * 128u;
    const uint32_t nb_base  = (uint32_t)((mid >> 1) * 8) * 2u;

    const uint32_t* pA0h = whi + (size_t)((wid * 2 + 0) * KS) * 128 + lane * 4;
    const uint32_t* pA0l = wlo + (size_t)((wid * 2 + 0) * KS) * 128 + lane * 4;
    const uint32_t* pA1h = whi + (size_t)((wid * 2 + 1) * KS) * 128 + lane * 4;
    const uint32_t* pA1l = wlo + (size_t)((wid * 2 + 1) * KS) * 128 + lane * 4;

    // prefetch A for ks=0
    uint4 Ah0 = *(const uint4*)pA0h;
    uint4 Al0 = *(const uint4*)pA0l;
    uint4 Ah1 = *(const uint4*)pA1h;
    uint4 Al1 = *(const uint4*)pA1l;

#pragma unroll 1
    for (int ks = 0; ks < KS; ++ks) {
        // ---- prefetch next A (issued before any consumer of current A) ----
        uint4 nAh0, nAl0, nAh1, nAl1;
        if (ks + 1 < KS) {
            nAh0 = *(const uint4*)(pA0h + (ks + 1) * 128);
            nAl0 = *(const uint4*)(pA0l + (ks + 1) * 128);
            nAh1 = *(const uint4*)(pA1h + (ks + 1) * 128);
            nAl1 = *(const uint4*)(pA1l + (ks + 1) * 128);
        }

        const uint32_t kbase = (uint32_t)ks * 16u * 128u + krow_off;

        // ---- two half-batches of 4 n-tiles (reg budget for A prefetch) ----
#pragma unroll
        for (int h = 0; h < 2; ++h) {
            uint32_t Bh[8], Bl[8];
#pragma unroll
            for (int j = 0; j < 2; ++j) {
                uint32_t nb = ((uint32_t)(h * 2 + j) * 32u + nb_base) ^ rswz;
                ldmx4t(Bh[4 * j], Bh[4 * j + 1], Bh[4 * j + 2], Bh[4 * j + 3],
                       shi + kbase + nb);
                ldmx4t(Bl[4 * j], Bl[4 * j + 1], Bl[4 * j + 2], Bl[4 * j + 3],
                       slo + kbase + nb);
            }
            // product-major interleave: acc reuse distance = 8 MMAs.
            // order: Ah*Bh, Al*Bh (Bh prefared), Ah*Bl last (Bl latency cover)
#pragma unroll
            for (int ntl = 0; ntl < 4; ++ntl) {
                const int nt = h * 4 + ntl;
                mma16816(acc[0][nt], Ah0, Bh[ntl * 2], Bh[ntl * 2 + 1]);
                mma16816(acc[1][nt], Ah1, Bh[ntl * 2], Bh[ntl * 2 + 1]);
            }
#pragma unroll
            for (int ntl = 0; ntl < 4; ++ntl) {
                const int nt = h * 4 + ntl;
                mma16816(acc[0][nt], Al0, Bh[ntl * 2], Bh[ntl * 2 + 1]);
                mma16816(acc[1][nt], Al1, Bh[ntl * 2], Bh[ntl * 2 + 1]);
            }
#pragma unroll
            for (int ntl = 0; ntl < 4; ++ntl) {
                const int nt = h * 4 + ntl;
                mma16816(acc[0][nt], Ah0, Bl[ntl * 2], Bl[ntl * 2 + 1]);
                mma16816(acc[1][nt], Ah1, Bl[ntl * 2], Bl[ntl * 2 + 1]);
            }
        }
        Ah0 = nAh0; Al0 = nAl0; Ah1 = nAh1; Al1 = nAl1;
    }

    // ---- sin + hi/lo split into acc regs BEFORE the read-barrier ----
    // hi = mantissa truncation (mask), lo = exact remainder rounded to bf16.
#pragma unroll
    for (int mtl = 0; mtl < 2; ++mtl) {
        const int row0 = wid * 32 + mtl * 16 + r;
        const float ob0 = OMEGA0 * __ldg(bias + row0);
        const float ob1 = OMEGA0 * __ldg(bias + row0 + 8);
#pragma unroll
        for (int nt = 0; nt < 8; ++nt) {
            float v00 = __sinf(fmaf(OMEGA0, acc[mtl][nt][0], ob0));
            float v01 = __sinf(fmaf(OMEGA0, acc[mtl][nt][1], ob0));
            float v10 = __sinf(fmaf(OMEGA0, acc[mtl][nt][2], ob1));
            float v11 = __sinf(fmaf(OMEGA0, acc[mtl][nt][3], ob1));
            uint32_t u00 = __float_as_uint(v00), u01 = __float_as_uint(v01);
            uint32_t u10 = __float_as_uint(v10), u11 = __float_as_uint(v11);
            uint32_t hp0 = __byte_perm(u00, u01, 0x7632);
            uint32_t hp1 = __byte_perm(u10, u11, 0x7632);
            float f00 = __uint_as_float(u00 & 0xFFFF0000u);
            float f01 = __uint_as_float(u01 & 0xFFFF0000u);
            float f10 = __uint_as_float(u10 & 0xFFFF0000u);
            float f11 = __uint_as_float(u11 & 0xFFFF0000u);
            uint32_t lp0, lp1;
            asm("cvt.rn.bf16x2.f32 %0, %1, %2;"
                : "=r"(lp0) : "f"(v01 - f01), "f"(v00 - f00));
            asm("cvt.rn.bf16x2.f32 %0, %1, %2;"
                : "=r"(lp1) : "f"(v11 - f11), "f"(v10 - f10));
            acc[mtl][nt][0] = __uint_as_float(hp0);
            acc[mtl][nt][1] = __uint_as_float(hp1);
            acc[mtl][nt][2] = __uint_as_float(lp0);
            acc[mtl][nt][3] = __uint_as_float(lp1);
        }
    }
    __syncthreads();   // all reads of act done -> safe to overwrite in place

#pragma unroll
    for (int mtl = 0; mtl < 2; ++mtl) {
        const int row0 = wid * 32 + mtl * 16 + r;
        const int row1 = row0 + 8;
        const uint32_t sw0 = ((uint32_t)row0 & 7u) << 4;
        const uint32_t sw1 = ((uint32_t)row1 & 7u) << 4;
#pragma unroll
        for (int nt = 0; nt < 8; ++nt) {
            const int n = nt * 8 + cq * 2;
            uint32_t off0 = (uint32_t)row0 * 128u + (((uint32_t)n * 2u) ^ sw0);
            uint32_t off1 = (uint32_t)row1 * 128u + (((uint32_t)n * 2u) ^ sw1);
            *(uint32_t*)(sm + SM_HI + off0) = __float_as_uint(acc[mtl][nt][0]);
            *(uint32_t*)(sm + SM_HI + off1) = __float_as_uint(acc[mtl][nt][1]);
            *(uint32_t*)(sm + SM_LO + off0) = __float_as_uint(acc[mtl][nt][2]);
            *(uint32_t*)(sm + SM_LO + off1) = __float_as_uint(acc[mtl][nt][3]);
        }
    }
    __syncthreads();   // next layer may read
}

// ---------------- main kernel ----------------
__global__ void __launch_bounds__(THREADS, 1)
inr_mma_kernel(const float* __restrict__ coords,
               const float* __restrict__ B_ff,
               const float* __restrict__ b_first,
               const float* __restrict__ b_hidden,
               const float* __restrict__ W_out,
               const float* __restrict__ b_out,
               float* __restrict__ out, int L)
{
    extern __shared__ unsigned char sm[];
    float* wout = (float*)(sm + SM_WOUT);
    float* cs   = (float*)(sm + SM_CS);
    float* bff  = (float*)(sm + SM_BFF);
    const uint32_t shi = smem_u32(sm + SM_HI);
    const uint32_t slo = smem_u32(sm + SM_LO);

    const int tid  = threadIdx.x;
    const int wid  = tid >> 5;
    const int lane = tid & 31;
    const int p0   = blockIdx.x * 64;

    if (tid < 192) {
        int g = p0 * 3 + tid;
        cs[tid] = (g < L * 3) ? coords[g] : 0.0f;
    }
    for (int i = tid; i < 384; i += THREADS) bff[i] = B_ff[i];
    __syncthreads();

    // Fourier features. sin(2*pi*t) == sin(2*pi*(t - rint(t))): exact
    // reduction before the 2*pi scale keeps the fast __sinf path accurate.
    for (int e = tid; e < 8192; e += THREADS) {
        int j = e >> 6, m = e & 63;
        float t = cs[m * 3 + 0] * bff[j] +
                  cs[m * 3 + 1] * bff[128 + j] +
                  cs[m * 3 + 2] * bff[256 + j];
        float f = t - rintf(t);
        float ang = TWO_PI_F * f;
        store1(sm, j, m, __sinf(ang));
        store1(sm, 128 + j, m, __cosf(ang));
    }
    __syncthreads();

    // layer 0: K=256 (16 k-steps)
    run_layer<16>(sm, shi, slo, g_wfrag, g_wfrag + PLANE_U32, b_first, wid, lane);
    // hidden layers: K=512 (32 k-steps)
#pragma unroll 1
    for (int l = 0; l < 5; ++l) {
        const size_t base = (size_t)(512 + l * 1024) * 128;
        run_layer<32>(sm, shi, slo, g_wfrag + base,
                      g_wfrag + PLANE_U32 + base,
                      b_hidden + l * 512, wid, lane);
    }

    // ---- output linear 512 -> 3: all 512 threads (8 k-slices per point) ----
    for (int f = tid; f < 1536; f += THREADS) wout[f] = W_out[f];
    __syncthreads();
    {
        const int p = tid >> 3;        // point 0..63
        const int s = tid & 7;         // k-slice 0..7
        float a0 = 0.0f, a1 = 0.0f, a2 = 0.0f;
#pragma unroll 4
        for (int kk = 0; kk < 64; ++kk) {
            const int k = s * 64 + kk;
            uint32_t off = (uint32_t)k * 128u +
                           (((uint32_t)p * 2u) ^ (((uint32_t)k & 7u) << 4));
            float hv = bff2f(*(uint16_t*)(sm + SM_HI + off)) +
                       bff2f(*(uint16_t*)(sm + SM_LO + off));
            a0 = fmaf(hv, wout[k], a0);
            a1 = fmaf(hv, wout[512 + k], a1);
            a2 = fmaf(hv, wout[1024 + k], a2);
        }
#pragma unroll
        for (int d = 4; d >= 1; d >>= 1) {
            a0 += __shfl_down_sync(0xFFFFFFFFu, a0, d);
            a1 += __shfl_down_sync(0xFFFFFFFFu, a1, d);
            a2 += __shfl_down_sync(0xFFFFFFFFu, a2, d);
        }
        if (s == 0) {
            int gp = p0 + p;
            if (gp < L) {
                out[gp * 3 + 0] = a0 + __ldg(b_out + 0);
                out[gp * 3 + 1] = a1 + __ldg(b_out + 1);
                out[gp * 3 + 2] = a2 + __ldg(b_out + 2);
            }
        }
    }
}

// ---------------- launcher ----------------
extern "C" void kernel_launch(void* const* d_in, const int* in_sizes, int n_in,
                              void* d_out, int out_size) {
    const float* coords   = (const float*)d_in[0];
    const float* B_ff     = (const float*)d_in[1];
    const float* W_first  = (const float*)d_in[2];
    const float* b_first  = (const float*)d_in[3];
    const float* W_hidden = (const float*)d_in[4];
    const float* b_hidden = (const float*)d_in[5];
    const float* W_out    = (const float*)d_in[6];
    const float* b_out    = (const float*)d_in[7];
    float* out = (float*)d_out;

    int L = in_sizes[0] / 3;
    int tiles = (L + 63) / 64;

    const int prep_n = 2 * PLANE_U32;
    prep_weights<<<(prep_n + 255) / 256, 256>>>(W_first, W_hidden);

    cudaFuncSetAttribute(inr_mma_kernel,
                         cudaFuncAttributeMaxDynamicSharedMemorySize,
                         SMEM_BYTES);
    inr_mma_kernel<<<tiles, THREADS, SMEM_BYTES>>>(
        coords, B_ff, b_first, b_hidden, W_out, b_out, out, L);
}

// round 10
// speedup vs baseline: 1.4978x; 1.4398x over previous
#include <cuda_runtime.h>
#include <cuda_fp16.h>
#include <math.h>
#include <stdint.h>

// ===========================================================================
// Fused INR via warp-level mma.sync, fp16 2-product split, fp32 accum.
//   weights: fp16 hi + fp16 lo planes (exact to ~2^-22, prep kernel)
//   acts   : single fp16 plane in swizzled SMEM
//   per k-step: 32 MMAs (vs 48 in bf16 3-product) -> -33% tensor work
// ===========================================================================

#define OMEGA0    30.0f
#define TWO_PI_F  6.283185307179586f
#define THREADS   512

#define NTILES    (512 + 5 * 1024)      // 5632 (mt,ks) tiles total
#define PLANE_U32 (NTILES * 128)        // u32 per plane (tile=128 u32)

__device__ __align__(16) uint32_t g_wfrag[2 * PLANE_U32];   // hi plane, lo plane

// ---- SMEM layout (bytes) ----
#define SM_WOUT  0                       // 1536 floats
#define SM_CS    6144                    // 192 floats
#define SM_BFF   6912                    // 384 floats
#define SM_HI    9216                    // act plane: 512 rows x 128B
#define SMEM_BYTES (SM_HI + 65536)       // 74752

// ---------------- helpers ----------------
__device__ __forceinline__ uint32_t smem_u32(const void* p) {
    uint32_t a;
    asm("{ .reg .u64 t; cvta.to.shared.u64 t, %1; cvt.u32.u64 %0, t; }"
        : "=r"(a) : "l"(p));
    return a;
}
__device__ __forceinline__ void mma16816(float* d, const uint4& a,
                                         uint32_t b0, uint32_t b1) {
    asm volatile(
        "mma.sync.aligned.m16n8k16.row.col.f32.f16.f16.f32 "
        "{%0,%1,%2,%3}, {%4,%5,%6,%7}, {%8,%9}, {%0,%1,%2,%3};"
        : "+f"(d[0]), "+f"(d[1]), "+f"(d[2]), "+f"(d[3])
        : "r"(a.x), "r"(a.y), "r"(a.z), "r"(a.w), "r"(b0), "r"(b1));
}
__device__ __forceinline__ void ldmx4t(uint32_t& r0, uint32_t& r1,
                                       uint32_t& r2, uint32_t& r3,
                                       uint32_t addr) {
    asm volatile(
        "ldmatrix.sync.aligned.m8n8.x4.trans.shared.b16 {%0,%1,%2,%3}, [%4];"
        : "=r"(r0), "=r"(r1), "=r"(r2), "=r"(r3) : "r"(addr));
}
__device__ __forceinline__ uint16_t hfb(float v) {
    __half h = __float2half_rn(v);
    return *reinterpret_cast<uint16_t*>(&h);
}
__device__ __forceinline__ float hff(uint16_t b) {
    __half h = *reinterpret_cast<__half*>(&b);
    return __half2float(h);
}

// store v (fp16) to (row, col n) in the act plane, swizzled
__device__ __forceinline__ void store1(unsigned char* sm, int row, int n, float v) {
    uint32_t off = (uint32_t)row * 128u + (((uint32_t)n * 2u) ^ (((uint32_t)row & 7u) << 4));
    *(uint16_t*)(sm + SM_HI + off) = hfb(v);
}

// ---------------- weight prep: fp32 -> fragment-ordered fp16 hi/lo ----------
__global__ void prep_weights(const float* __restrict__ Wf,
                             const float* __restrict__ Wh) {
    int idx = blockIdx.x * blockDim.x + threadIdx.x;
    if (idx >= 2 * PLANE_U32) return;
    int p   = idx / PLANE_U32;
    int rem = idx - p * PLANE_U32;
    int tile = rem >> 7;
    int li   = rem & 127;
    int lane = li >> 2, q = li & 3;

    const float* src; int K, mt, ks;
    if (tile < 512) { mt = tile >> 4; ks = tile & 15; K = 256; src = Wf; }
    else {
        int th = tile - 512;
        int l = th >> 10, tt = th & 1023;
        mt = tt >> 5; ks = tt & 31; K = 512;
        src = Wh + (size_t)l * 512 * 512;
    }
    int r  = lane >> 2, c2 = (lane & 3) * 2;
    int row = mt * 16 + r + (q & 1) * 8;
    int k   = ks * 16 + c2 + (q >> 1) * 8;
    float w0 = src[(size_t)row * K + k];
    float w1 = src[(size_t)row * K + k + 1];
    uint16_t h0 = hfb(w0), h1 = hfb(w1);
    uint16_t o0, o1;
    if (p == 0) { o0 = h0; o1 = h1; }
    else        { o0 = hfb(w0 - hff(h0)); o1 = hfb(w1 - hff(h1)); }
    g_wfrag[idx] = ((uint32_t)o1 << 16) | (uint32_t)o0;
}

// ---------------- one sine layer (KS k-steps of 16) ----------------
template <int KS>
__device__ __forceinline__ void run_layer(
    unsigned char* sm, uint32_t shi,
    const uint32_t* __restrict__ whi,
    const uint32_t* __restrict__ wlo,
    const float* __restrict__ bias,
    int wid, int lane)
{
    float acc[2][8][4];
#pragma unroll
    for (int a = 0; a < 2; ++a)
#pragma unroll
        for (int b = 0; b < 8; ++b)
#pragma unroll
            for (int c = 0; c < 4; ++c) acc[a][b][c] = 0.0f;

    const int r  = lane >> 2;
    const int cq = lane & 3;
    const int mid  = lane >> 3;
    const int rrow = lane & 7;
    const uint32_t rswz = (uint32_t)rrow << 4;
    const uint32_t krow_off = ((uint32_t)((mid & 1) * 8 + rrow)) * 128u;
    const uint32_t nb_base  = (uint32_t)((mid >> 1) * 8) * 2u;

    const uint32_t* pA0h = whi + (size_t)((wid * 2 + 0) * KS) * 128 + lane * 4;
    const uint32_t* pA0l = wlo + (size_t)((wid * 2 + 0) * KS) * 128 + lane * 4;
    const uint32_t* pA1h = whi + (size_t)((wid * 2 + 1) * KS) * 128 + lane * 4;
    const uint32_t* pA1l = wlo + (size_t)((wid * 2 + 1) * KS) * 128 + lane * 4;

    // prefetch A for ks=0
    uint4 Ah0 = *(const uint4*)pA0h;
    uint4 Al0 = *(const uint4*)pA0l;
    uint4 Ah1 = *(const uint4*)pA1h;
    uint4 Al1 = *(const uint4*)pA1l;

#pragma unroll 1
    for (int ks = 0; ks < KS; ++ks) {
        // prefetch next A (issued before any consumer of current A)
        uint4 nAh0, nAl0, nAh1, nAl1;
        if (ks + 1 < KS) {
            nAh0 = *(const uint4*)(pA0h + (ks + 1) * 128);
            nAl0 = *(const uint4*)(pA0l + (ks + 1) * 128);
            nAh1 = *(const uint4*)(pA1h + (ks + 1) * 128);
            nAl1 = *(const uint4*)(pA1l + (ks + 1) * 128);
        }

        // ---- B fragments: single act plane, 4x ldmatrix.x4.trans = n64 ----
        uint32_t B[16];
        const uint32_t kbase = (uint32_t)ks * 16u * 128u + krow_off;
#pragma unroll
        for (int j = 0; j < 4; ++j) {
            uint32_t nb = ((uint32_t)j * 32u + nb_base) ^ rswz;
            ldmx4t(B[4 * j], B[4 * j + 1], B[4 * j + 2], B[4 * j + 3],
                   shi + kbase + nb);
        }

        // ---- MMAs: 2 products x 2 m-tiles x 8 n-tiles = 32 ----
#pragma unroll
        for (int nt = 0; nt < 8; ++nt) {
            mma16816(acc[0][nt], Ah0, B[nt * 2], B[nt * 2 + 1]);
            mma16816(acc[1][nt], Ah1, B[nt * 2], B[nt * 2 + 1]);
        }
#pragma unroll
        for (int nt = 0; nt < 8; ++nt) {
            mma16816(acc[0][nt], Al0, B[nt * 2], B[nt * 2 + 1]);
            mma16816(acc[1][nt], Al1, B[nt * 2], B[nt * 2 + 1]);
        }
        Ah0 = nAh0; Al0 = nAl0; Ah1 = nAh1; Al1 = nAl1;
    }

    // ---- sin + fp16 pack into acc regs BEFORE the read-barrier ----
#pragma unroll
    for (int mtl = 0; mtl < 2; ++mtl) {
        const int row0 = wid * 32 + mtl * 16 + r;
        const float ob0 = OMEGA0 * __ldg(bias + row0);
        const float ob1 = OMEGA0 * __ldg(bias + row0 + 8);
#pragma unroll
        for (int nt = 0; nt < 8; ++nt) {
            float v00 = __sinf(fmaf(OMEGA0, acc[mtl][nt][0], ob0));
            float v01 = __sinf(fmaf(OMEGA0, acc[mtl][nt][1], ob0));
            float v10 = __sinf(fmaf(OMEGA0, acc[mtl][nt][2], ob1));
            float v11 = __sinf(fmaf(OMEGA0, acc[mtl][nt][3], ob1));
            uint32_t hp0, hp1;
            asm("cvt.rn.f16x2.f32 %0, %1, %2;"
                : "=r"(hp0) : "f"(v01), "f"(v00));
            asm("cvt.rn.f16x2.f32 %0, %1, %2;"
                : "=r"(hp1) : "f"(v11), "f"(v10));
            acc[mtl][nt][0] = __uint_as_float(hp0);
            acc[mtl][nt][1] = __uint_as_float(hp1);
        }
    }
    __syncthreads();   // all reads of act done -> safe to overwrite in place

#pragma unroll
    for (int mtl = 0; mtl < 2; ++mtl) {
        const int row0 = wid * 32 + mtl * 16 + r;
        const int row1 = row0 + 8;
        const uint32_t sw0 = ((uint32_t)row0 & 7u) << 4;
        const uint32_t sw1 = ((uint32_t)row1 & 7u) << 4;
#pragma unroll
        for (int nt = 0; nt < 8; ++nt) {
            const int n = nt * 8 + cq * 2;
            uint32_t off0 = (uint32_t)row0 * 128u + (((uint32_t)n * 2u) ^ sw0);
            uint32_t off1 = (uint32_t)row1 * 128u + (((uint32_t)n * 2u) ^ sw1);
            *(uint32_t*)(sm + SM_HI + off0) = __float_as_uint(acc[mtl][nt][0]);
            *(uint32_t*)(sm + SM_HI + off1) = __float_as_uint(acc[mtl][nt][1]);
        }
    }
    __syncthreads();   // next layer may read
}

// ---------------- main kernel ----------------
__global__ void __launch_bounds__(THREADS, 1)
inr_mma_kernel(const float* __restrict__ coords,
               const float* __restrict__ B_ff,
               const float* __restrict__ b_first,
               const float* __restrict__ b_hidden,
               const float* __restrict__ W_out,
               const float* __restrict__ b_out,
               float* __restrict__ out, int L)
{
    extern __shared__ unsigned char sm[];
    float* wout = (float*)(sm + SM_WOUT);
    float* cs   = (float*)(sm + SM_CS);
    float* bff  = (float*)(sm + SM_BFF);
    const uint32_t shi = smem_u32(sm + SM_HI);

    const int tid  = threadIdx.x;
    const int wid  = tid >> 5;
    const int lane = tid & 31;
    const int p0   = blockIdx.x * 64;

    if (tid < 192) {
        int g = p0 * 3 + tid;
        cs[tid] = (g < L * 3) ? coords[g] : 0.0f;
    }
    for (int i = tid; i < 384; i += THREADS) bff[i] = B_ff[i];
    __syncthreads();

    // Fourier features. sin(2*pi*t) == sin(2*pi*(t - rint(t))): exact
    // reduction before the 2*pi scale keeps the fast __sinf path accurate.
    for (int e = tid; e < 8192; e += THREADS) {
        int j = e >> 6, m = e & 63;
        float t = cs[m * 3 + 0] * bff[j] +
                  cs[m * 3 + 1] * bff[128 + j] +
                  cs[m * 3 + 2] * bff[256 + j];
        float f = t - rintf(t);
        float ang = TWO_PI_F * f;
        store1(sm, j, m, __sinf(ang));
        store1(sm, 128 + j, m, __cosf(ang));
    }
    __syncthreads();

    // layer 0: K=256 (16 k-steps)
    run_layer<16>(sm, shi, g_wfrag, g_wfrag + PLANE_U32, b_first, wid, lane);
    // hidden layers: K=512 (32 k-steps)
#pragma unroll 1
    for (int l = 0; l < 5; ++l) {
        const size_t base = (size_t)(512 + l * 1024) * 128;
        run_layer<32>(sm, shi, g_wfrag + base,
                      g_wfrag + PLANE_U32 + base,
                      b_hidden + l * 512, wid, lane);
    }

    // ---- output linear 512 -> 3: all 512 threads (8 k-slices per point) ----
    for (int f = tid; f < 1536; f += THREADS) wout[f] = W_out[f];
    __syncthreads();
    {
        const int p = tid >> 3;        // point 0..63
        const int s = tid & 7;         // k-slice 0..7
        float a0 = 0.0f, a1 = 0.0f, a2 = 0.0f;
#pragma unroll 4
        for (int kk = 0; kk < 64; ++kk) {
            const int k = s * 64 + kk;
            uint32_t off = (uint32_t)k * 128u +
                           (((uint32_t)p * 2u) ^ (((uint32_t)k & 7u) << 4));
            float hv = hff(*(uint16_t*)(sm + SM_HI + off));
            a0 = fmaf(hv, wout[k], a0);
            a1 = fmaf(hv, wout[512 + k], a1);
            a2 = fmaf(hv, wout[1024 + k], a2);
        }
#pragma unroll
        for (int d = 4; d >= 1; d >>= 1) {
            a0 += __shfl_down_sync(0xFFFFFFFFu, a0, d);
            a1 += __shfl_down_sync(0xFFFFFFFFu, a1, d);
            a2 += __shfl_down_sync(0xFFFFFFFFu, a2, d);
        }
        if (s == 0) {
            int gp = p0 + p;
            if (gp < L) {
                out[gp * 3 + 0] = a0 + __ldg(b_out + 0);
                out[gp * 3 + 1] = a1 + __ldg(b_out + 1);
                out[gp * 3 + 2] = a2 + __ldg(b_out + 2);
            }
        }
    }
}

// ---------------- launcher ----------------
extern "C" void kernel_launch(void* const* d_in, const int* in_sizes, int n_in,
                              void* d_out, int out_size) {
    const float* coords   = (const float*)d_in[0];
    const float* B_ff     = (const float*)d_in[1];
    const float* W_first  = (const float*)d_in[2];
    const float* b_first  = (const float*)d_in[3];
    const float* W_hidden = (const float*)d_in[4];
    const float* b_hidden = (const float*)d_in[5];
    const float* W_out    = (const float*)d_in[6];
    const float* b_out    = (const float*)d_in[7];
    float* out = (float*)d_out;

    int L = in_sizes[0] / 3;
    int tiles = (L + 63) / 64;

    const int prep_n = 2 * PLANE_U32;
    prep_weights<<<(prep_n + 255) / 256, 256>>>(W_first, W_hidden);

    cudaFuncSetAttribute(inr_mma_kernel,
                         cudaFuncAttributeMaxDynamicSharedMemorySize,
                         SMEM_BYTES);
    inr_mma_kernel<<<tiles, THREADS, SMEM_BYTES>>>(
        coords, B_ff, b_first, b_hidden, W_out, b_out, out, L);
}